// round 1
// baseline (speedup 1.0000x reference)
#include <cuda_runtime.h>

#define HWSZ 65536           // 256*256
#define FEAT (16*64*HWSZ)    // 67,108,864 floats = 256 MB

// scratch feature maps (allocation-free: __device__ globals)
__device__ float g_featA[FEAT];
__device__ float g_featB[FEAT];

__device__ __forceinline__ float prelu_f(float v, float a) {
    return v >= 0.f ? v : a * v;
}

// ---------------------------------------------------------------------------
// CS sampling conv: outcsy[n,f,by,bx] = sum_{i,j} x[n, by*32+i, bx*32+j]*Wcs[f,i,j]
// grid (8 pg=by, 16 n), 256 threads (thread = filter f). Each CTA does bx=0..7.
// ---------------------------------------------------------------------------
__global__ void cs_kernel(const float* __restrict__ x,
                          const float* __restrict__ Wcs,
                          float* __restrict__ csy) {
    const int pg = blockIdx.x;   // by
    const int n  = blockIdx.y;
    const int f  = threadIdx.x;
    __shared__ float sX[8][32];
    __shared__ float sW[256][33];

    float acc[8] = {0.f,0.f,0.f,0.f,0.f,0.f,0.f,0.f};

    for (int k0 = 0; k0 < 1024; k0 += 32) {
        const int i = k0 >> 5;  // row within 32x32 block
        {   // 256 elems: one per thread. p = bx, kk = j
            int p = threadIdx.x >> 5, kk = threadIdx.x & 31;
            sX[p][kk] = x[n * HWSZ + (pg * 32 + i) * 256 + p * 32 + kk];
        }
        for (int e = threadIdx.x; e < 8192; e += 256) {
            int ff = e >> 5, kk = e & 31;
            sW[ff][kk] = Wcs[ff * 1024 + k0 + kk];
        }
        __syncthreads();
#pragma unroll
        for (int kk = 0; kk < 32; kk++) {
            float w = sW[f][kk];
#pragma unroll
            for (int p = 0; p < 8; p++) acc[p] += sX[p][kk] * w;
        }
        __syncthreads();
    }
#pragma unroll
    for (int p = 0; p < 8; p++)
        csy[(n * 256 + f) * 64 + pg * 8 + p] = acc[p];
}

// ---------------------------------------------------------------------------
// Init reconstruction (1x1 conv 256->1024) fused with depth-to-space scatter.
// initrec[n, by*32+i, bx*32+j] = sum_k csy[n,k,by,bx] * Wi[c,k], c=j*32+i
// grid (8 cgrp of 128 channels, 16 n), 256 threads.
// ---------------------------------------------------------------------------
__global__ void init_kernel(const float* __restrict__ csy,
                            const float* __restrict__ Wi,
                            float* __restrict__ initrec) {
    const int cb = blockIdx.x * 128;
    const int n  = blockIdx.y;
    const int cg  = threadIdx.x >> 3;  // 0..31 (4 channels each)
    const int pgl = threadIdx.x & 7;   // 0..7  (8 positions each)
    __shared__ float sX[32][64];
    __shared__ float sW[128][33];

    float acc[4][8] = {};

    for (int k0 = 0; k0 < 256; k0 += 32) {
        for (int e = threadIdx.x; e < 2048; e += 256) {
            int kk = e >> 6, pos = e & 63;
            sX[kk][pos] = csy[(n * 256 + k0 + kk) * 64 + pos];
        }
        for (int e = threadIdx.x; e < 4096; e += 256) {
            int cl = e >> 5, kk = e & 31;
            sW[cl][kk] = Wi[(cb + cl) * 256 + k0 + kk];
        }
        __syncthreads();
#pragma unroll
        for (int kk = 0; kk < 32; kk++) {
            float w0 = sW[cg * 4 + 0][kk];
            float w1 = sW[cg * 4 + 1][kk];
            float w2 = sW[cg * 4 + 2][kk];
            float w3 = sW[cg * 4 + 3][kk];
#pragma unroll
            for (int pp = 0; pp < 8; pp++) {
                float xv = sX[kk][pgl * 8 + pp];
                acc[0][pp] += w0 * xv;
                acc[1][pp] += w1 * xv;
                acc[2][pp] += w2 * xv;
                acc[3][pp] += w3 * xv;
            }
        }
        __syncthreads();
    }
    // scatter: channel c = j*32 + i -> pixel (by*32+i, bx*32+j)
#pragma unroll
    for (int jc = 0; jc < 4; jc++) {
        int c  = cb + cg * 4 + jc;
        int jj = c >> 5;
        int ii = c & 31;
#pragma unroll
        for (int pp = 0; pp < 8; pp++) {
            int pos = pgl * 8 + pp;
            int by = pos >> 3, bx = pos & 7;
            initrec[n * HWSZ + (by * 32 + ii) * 256 + (bx * 32 + jj)] = acc[jc][pp];
        }
    }
}

// ---------------------------------------------------------------------------
// First conv: 1 -> 64 channels, 3x3 pad 1, PReLU(a_main)
// grid (16 tx, 16 ty, 16 n), 256 threads (1 px each, loop over 64 co).
// ---------------------------------------------------------------------------
__global__ void first_kernel(const float* __restrict__ initrec,
                             const float* __restrict__ Wf,
                             const float* __restrict__ aM,
                             float* __restrict__ out) {
    const int tx = blockIdx.x, ty = blockIdx.y, n = blockIdx.z;
    __shared__ float sI[18][18];
    __shared__ float sWf[576];

    for (int e = threadIdx.x; e < 324; e += 256) {
        int yy = e / 18, xx = e % 18;
        int gy = ty * 16 - 1 + yy, gx = tx * 16 - 1 + xx;
        float v = 0.f;
        if ((unsigned)gy < 256u && (unsigned)gx < 256u)
            v = initrec[n * HWSZ + gy * 256 + gx];
        sI[yy][xx] = v;
    }
    for (int e = threadIdx.x; e < 576; e += 256) sWf[e] = Wf[e];
    __syncthreads();

    const float a = aM[0];
    const int r = threadIdx.x >> 4, c = threadIdx.x & 15;
    float v[9];
#pragma unroll
    for (int ky = 0; ky < 3; ky++)
#pragma unroll
        for (int kx = 0; kx < 3; kx++)
            v[ky * 3 + kx] = sI[r + ky][c + kx];

    const int gy = ty * 16 + r, gx = tx * 16 + c;
    for (int co = 0; co < 64; co++) {
        float s = 0.f;
#pragma unroll
        for (int kk = 0; kk < 9; kk++) s += sWf[co * 9 + kk] * v[kk];
        out[((n * 64 + co) << 16) + (gy << 8) + gx] = prelu_f(s, a);
    }
}

// ---------------------------------------------------------------------------
// Main 64->64 3x3 conv, pad 1. Block: 16x16 spatial tile x all 64 co, one n.
// Thread: 16 co x 4 px register tile. Cin chunked by 8 through smem.
// RES=false: out = prelu(conv(in), a)
// RES=true : out = prelu(res + conv(in), a)   (res may alias out)
// ---------------------------------------------------------------------------
template <bool RES>
__global__ void __launch_bounds__(256, 2) blk_kernel(
    const float* __restrict__ in, const float* __restrict__ Wb,
    const float* __restrict__ aB, float* __restrict__ out,
    const float* __restrict__ res) {
    const int tx = blockIdx.x, ty = blockIdx.y, n = blockIdx.z;
    __shared__ float sIn[8][18][20];       // [ci][y][x], x padded to 20
    __shared__ float sW[8 * 9 * 68];       // [ci][kk][co], co-dim padded to 68 (16B-aligned rows)

    const int cog = threadIdx.x >> 6;          // 0..3
    const int pix = threadIdx.x & 63;          // 0..63
    const int row = pix >> 2;                  // 0..15
    const int col0 = (pix & 3) << 2;           // 0,4,8,12
    const int cobase = cog << 4;               // 0,16,32,48

    float acc[16][4];
#pragma unroll
    for (int c = 0; c < 16; c++)
#pragma unroll
        for (int p = 0; p < 4; p++) acc[c][p] = 0.f;

    for (int ci0 = 0; ci0 < 64; ci0 += 8) {
        for (int e = threadIdx.x; e < 2592; e += 256) {
            int ci = e / 324, r2 = e % 324, yy = r2 / 18, xx = r2 % 18;
            int gy = ty * 16 - 1 + yy, gx = tx * 16 - 1 + xx;
            float v = 0.f;
            if ((unsigned)gy < 256u && (unsigned)gx < 256u)
                v = in[((n * 64 + ci0 + ci) << 16) + (gy << 8) + gx];
            sIn[ci][yy][xx] = v;
        }
        for (int e = threadIdx.x; e < 4608; e += 256) {
            int co = e / 72, r2 = e % 72, ci = r2 / 9, kk = r2 % 9;
            sW[(ci * 9 + kk) * 68 + co] = Wb[co * 576 + (ci0 + ci) * 9 + kk];
        }
        __syncthreads();

#pragma unroll 1
        for (int ci = 0; ci < 8; ci++) {
#pragma unroll
            for (int ky = 0; ky < 3; ky++) {
                const float* ip = &sIn[ci][row + ky][col0];
                float4 i0 = *reinterpret_cast<const float4*>(ip);
                float2 i1 = *reinterpret_cast<const float2*>(ip + 4);
                float iv[6] = {i0.x, i0.y, i0.z, i0.w, i1.x, i1.y};
#pragma unroll
                for (int kx = 0; kx < 3; kx++) {
                    const float* wp = &sW[(ci * 9 + ky * 3 + kx) * 68 + cobase];
#pragma unroll
                    for (int cq = 0; cq < 4; cq++) {
                        float4 w4 = *reinterpret_cast<const float4*>(wp + cq * 4);
                        float wv[4] = {w4.x, w4.y, w4.z, w4.w};
#pragma unroll
                        for (int cj = 0; cj < 4; cj++) {
                            int c = cq * 4 + cj;
                            acc[c][0] += wv[cj] * iv[kx + 0];
                            acc[c][1] += wv[cj] * iv[kx + 1];
                            acc[c][2] += wv[cj] * iv[kx + 2];
                            acc[c][3] += wv[cj] * iv[kx + 3];
                        }
                    }
                }
            }
        }
        __syncthreads();
    }

    const float a = aB[0];
    const int gy = ty * 16 + row, gx0 = tx * 16 + col0;
#pragma unroll
    for (int c = 0; c < 16; c++) {
        int base = ((n * 64 + cobase + c) << 16) + (gy << 8) + gx0;
        float4 v = make_float4(acc[c][0], acc[c][1], acc[c][2], acc[c][3]);
        if (RES) {
            float4 rr = *reinterpret_cast<const float4*>(res + base);
            v.x += rr.x; v.y += rr.y; v.z += rr.z; v.w += rr.w;
        }
        v.x = prelu_f(v.x, a);
        v.y = prelu_f(v.y, a);
        v.z = prelu_f(v.z, a);
        v.w = prelu_f(v.w, a);
        *reinterpret_cast<float4*>(out + base) = v;
    }
}

// ---------------------------------------------------------------------------
// Last conv: (feat + initrec broadcast) -> 1 channel, 3x3 pad 1, no activation.
// grid (16,16,16), 256 threads, 1 px each.
// ---------------------------------------------------------------------------
__global__ void last_kernel(const float* __restrict__ feat,
                            const float* __restrict__ initrec,
                            const float* __restrict__ Wl,
                            float* __restrict__ out) {
    const int tx = blockIdx.x, ty = blockIdx.y, n = blockIdx.z;
    __shared__ float sInit[18][18];
    __shared__ float sIn[8][18][20];
    __shared__ float sWl[576];

    for (int e = threadIdx.x; e < 324; e += 256) {
        int yy = e / 18, xx = e % 18;
        int gy = ty * 16 - 1 + yy, gx = tx * 16 - 1 + xx;
        float v = 0.f;
        if ((unsigned)gy < 256u && (unsigned)gx < 256u)
            v = initrec[n * HWSZ + gy * 256 + gx];
        sInit[yy][xx] = v;
    }
    for (int e = threadIdx.x; e < 576; e += 256) sWl[e] = Wl[e];
    __syncthreads();

    const int r = threadIdx.x >> 4, c = threadIdx.x & 15;
    float acc = 0.f;

    for (int ci0 = 0; ci0 < 64; ci0 += 8) {
        for (int e = threadIdx.x; e < 2592; e += 256) {
            int ci = e / 324, r2 = e % 324, yy = r2 / 18, xx = r2 % 18;
            int gy = ty * 16 - 1 + yy, gx = tx * 16 - 1 + xx;
            float v = 0.f;
            if ((unsigned)gy < 256u && (unsigned)gx < 256u)
                v = feat[((n * 64 + ci0 + ci) << 16) + (gy << 8) + gx];
            sIn[ci][yy][xx] = v + sInit[yy][xx];   // broadcast-add initrec per channel
        }
        __syncthreads();
#pragma unroll 1
        for (int ci = 0; ci < 8; ci++) {
#pragma unroll
            for (int ky = 0; ky < 3; ky++)
#pragma unroll
                for (int kx = 0; kx < 3; kx++)
                    acc += sIn[ci][r + ky][c + kx] * sWl[(ci0 + ci) * 9 + ky * 3 + kx];
        }
        __syncthreads();
    }
    out[n * HWSZ + (ty * 16 + r) * 256 + (tx * 16 + c)] = acc;
}

// ---------------------------------------------------------------------------
extern "C" void kernel_launch(void* const* d_in, const int* in_sizes, int n_in,
                              void* d_out, int out_size) {
    (void)in_sizes; (void)n_in; (void)out_size;
    const float* x   = (const float*)d_in[0];
    const float* Wcs = (const float*)d_in[1];
    const float* Wi  = (const float*)d_in[2];
    const float* Wf  = (const float*)d_in[3];
    const float* Wb  = (const float*)d_in[4];
    const float* Wl  = (const float*)d_in[5];
    const float* aM  = (const float*)d_in[6];
    const float* aB  = (const float*)d_in[7];

    float* out     = (float*)d_out;             // [16,1,256,256]
    float* csy     = out + 16 * HWSZ;           // [16,256,8,8]
    float* initrec = csy + 16 * 256 * 64;       // [16,1,256,256]

    float *fA = nullptr, *fB = nullptr;
    cudaGetSymbolAddress((void**)&fA, g_featA);
    cudaGetSymbolAddress((void**)&fB, g_featB);

    cs_kernel<<<dim3(8, 16), 256>>>(x, Wcs, csy);
    init_kernel<<<dim3(8, 16), 256>>>(csy, Wi, initrec);
    first_kernel<<<dim3(16, 16, 16), 256>>>(initrec, Wf, aM, fA);

    for (int i = 0; i < 4; i++) {
        blk_kernel<false><<<dim3(16, 16, 16), 256>>>(fA, Wb, aB, fB, nullptr);
        blk_kernel<true><<<dim3(16, 16, 16), 256>>>(fB, Wb, aB, fA, fA);
    }
    last_kernel<<<dim3(16, 16, 16), 256>>>(fA, initrec, Wl, out);
}

// round 2
// speedup vs baseline: 1.1130x; 1.1130x over previous
#include <cuda_runtime.h>

#define HWSZ 65536           // 256*256
#define FEAT (16*64*HWSZ)    // 67,108,864 floats = 256 MB

// scratch feature maps (allocation-free: __device__ globals)
__device__ float g_featA[FEAT];
__device__ float g_featB[FEAT];

__device__ __forceinline__ float prelu_f(float v, float a) {
    return v >= 0.f ? v : a * v;
}

// ---- packed f32x2 helpers (sm_103a) --------------------------------------
__device__ __forceinline__ unsigned long long splat2(float v) {
    unsigned long long r;
    asm("mov.b64 %0, {%1, %1};" : "=l"(r) : "f"(v));
    return r;
}
__device__ __forceinline__ void fma2(unsigned long long& d,
                                     unsigned long long a,
                                     unsigned long long b) {
    asm("fma.rn.f32x2 %0, %1, %2, %0;" : "+l"(d) : "l"(a), "l"(b));
}
__device__ __forceinline__ void unpack2(unsigned long long v, float& lo, float& hi) {
    asm("mov.b64 {%0, %1}, %2;" : "=f"(lo), "=f"(hi) : "l"(v));
}

// ---------------------------------------------------------------------------
// CS sampling conv: outcsy[n,f,by,bx] = sum_{i,j} x[n, by*32+i, bx*32+j]*Wcs[f,i,j]
// ---------------------------------------------------------------------------
__global__ void cs_kernel(const float* __restrict__ x,
                          const float* __restrict__ Wcs,
                          float* __restrict__ csy) {
    const int pg = blockIdx.x;   // by
    const int n  = blockIdx.y;
    const int f  = threadIdx.x;
    __shared__ float sX[8][32];
    __shared__ float sW[256][33];

    float acc[8] = {0.f,0.f,0.f,0.f,0.f,0.f,0.f,0.f};

    for (int k0 = 0; k0 < 1024; k0 += 32) {
        const int i = k0 >> 5;  // row within 32x32 block
        {
            int p = threadIdx.x >> 5, kk = threadIdx.x & 31;
            sX[p][kk] = x[n * HWSZ + (pg * 32 + i) * 256 + p * 32 + kk];
        }
        for (int e = threadIdx.x; e < 8192; e += 256) {
            int ff = e >> 5, kk = e & 31;
            sW[ff][kk] = Wcs[ff * 1024 + k0 + kk];
        }
        __syncthreads();
#pragma unroll
        for (int kk = 0; kk < 32; kk++) {
            float w = sW[f][kk];
#pragma unroll
            for (int p = 0; p < 8; p++) acc[p] += sX[p][kk] * w;
        }
        __syncthreads();
    }
#pragma unroll
    for (int p = 0; p < 8; p++)
        csy[(n * 256 + f) * 64 + pg * 8 + p] = acc[p];
}

// ---------------------------------------------------------------------------
// Init reconstruction (1x1 conv 256->1024) fused with depth-to-space scatter.
// ---------------------------------------------------------------------------
__global__ void init_kernel(const float* __restrict__ csy,
                            const float* __restrict__ Wi,
                            float* __restrict__ initrec) {
    const int cb = blockIdx.x * 128;
    const int n  = blockIdx.y;
    const int cg  = threadIdx.x >> 3;  // 0..31 (4 channels each)
    const int pgl = threadIdx.x & 7;   // 0..7  (8 positions each)
    __shared__ float sX[32][64];
    __shared__ float sW[128][33];

    float acc[4][8] = {};

    for (int k0 = 0; k0 < 256; k0 += 32) {
        for (int e = threadIdx.x; e < 2048; e += 256) {
            int kk = e >> 6, pos = e & 63;
            sX[kk][pos] = csy[(n * 256 + k0 + kk) * 64 + pos];
        }
        for (int e = threadIdx.x; e < 4096; e += 256) {
            int cl = e >> 5, kk = e & 31;
            sW[cl][kk] = Wi[(cb + cl) * 256 + k0 + kk];
        }
        __syncthreads();
#pragma unroll
        for (int kk = 0; kk < 32; kk++) {
            float w0 = sW[cg * 4 + 0][kk];
            float w1 = sW[cg * 4 + 1][kk];
            float w2 = sW[cg * 4 + 2][kk];
            float w3 = sW[cg * 4 + 3][kk];
#pragma unroll
            for (int pp = 0; pp < 8; pp++) {
                float xv = sX[kk][pgl * 8 + pp];
                acc[0][pp] += w0 * xv;
                acc[1][pp] += w1 * xv;
                acc[2][pp] += w2 * xv;
                acc[3][pp] += w3 * xv;
            }
        }
        __syncthreads();
    }
#pragma unroll
    for (int jc = 0; jc < 4; jc++) {
        int c  = cb + cg * 4 + jc;
        int jj = c >> 5;
        int ii = c & 31;
#pragma unroll
        for (int pp = 0; pp < 8; pp++) {
            int pos = pgl * 8 + pp;
            int by = pos >> 3, bx = pos & 7;
            initrec[n * HWSZ + (by * 32 + ii) * 256 + (bx * 32 + jj)] = acc[jc][pp];
        }
    }
}

// ---------------------------------------------------------------------------
// First conv: 1 -> 64 channels, 3x3 pad 1, PReLU(a_main)
// ---------------------------------------------------------------------------
__global__ void first_kernel(const float* __restrict__ initrec,
                             const float* __restrict__ Wf,
                             const float* __restrict__ aM,
                             float* __restrict__ out) {
    const int tx = blockIdx.x, ty = blockIdx.y, n = blockIdx.z;
    __shared__ float sI[18][18];
    __shared__ float sWf[576];

    for (int e = threadIdx.x; e < 324; e += 256) {
        int yy = e / 18, xx = e % 18;
        int gy = ty * 16 - 1 + yy, gx = tx * 16 - 1 + xx;
        float v = 0.f;
        if ((unsigned)gy < 256u && (unsigned)gx < 256u)
            v = initrec[n * HWSZ + gy * 256 + gx];
        sI[yy][xx] = v;
    }
    for (int e = threadIdx.x; e < 576; e += 256) sWf[e] = Wf[e];
    __syncthreads();

    const float a = aM[0];
    const int r = threadIdx.x >> 4, c = threadIdx.x & 15;
    float v[9];
#pragma unroll
    for (int ky = 0; ky < 3; ky++)
#pragma unroll
        for (int kx = 0; kx < 3; kx++)
            v[ky * 3 + kx] = sI[r + ky][c + kx];

    const int gy = ty * 16 + r, gx = tx * 16 + c;
    for (int co = 0; co < 64; co++) {
        float s = 0.f;
#pragma unroll
        for (int kk = 0; kk < 9; kk++) s += sWf[co * 9 + kk] * v[kk];
        out[((n * 64 + co) << 16) + (gy << 8) + gx] = prelu_f(s, a);
    }
}

// ---------------------------------------------------------------------------
// Main 64->64 3x3 conv, pad 1.  16x16 spatial tile x all 64 co, one n per CTA.
// Thread: 16 co x 4 px register tile, with co packed in f32x2 PAIRS so each
// fma.rn.f32x2 does 2 FMAs in one issue slot. Weights come pre-packed from
// smem (co contiguous); only 6 input splats per (ci,ky).
// RES=false: out = prelu(conv(in), a)
// RES=true : out = prelu(res + conv(in), a)   (res may alias out)
// ---------------------------------------------------------------------------
template <bool RES>
__global__ void __launch_bounds__(256, 2) blk_kernel(
    const float* __restrict__ in, const float* __restrict__ Wb,
    const float* __restrict__ aB, float* __restrict__ out,
    const float* __restrict__ res) {
    const int tx = blockIdx.x, ty = blockIdx.y, n = blockIdx.z;
    __shared__ float sIn[8][18][20];       // [ci][y][x], x padded to 20
    __shared__ float sW[8 * 9 * 68];       // [ci][kk][co], co padded to 68 (16B rows)

    const int cog = threadIdx.x >> 6;          // 0..3
    const int pix = threadIdx.x & 63;          // 0..63
    const int row = pix >> 2;                  // 0..15
    const int col0 = (pix & 3) << 2;           // 0,4,8,12
    const int cobase = cog << 4;               // 0,16,32,48

    // acc2[c2][p] holds fp32 pair (co=cobase+2*c2, co=cobase+2*c2+1) at pixel p
    unsigned long long acc2[8][4];
#pragma unroll
    for (int c = 0; c < 8; c++)
#pragma unroll
        for (int p = 0; p < 4; p++) acc2[c][p] = 0ull;

    for (int ci0 = 0; ci0 < 64; ci0 += 8) {
        for (int e = threadIdx.x; e < 2592; e += 256) {
            int ci = e / 324, r2 = e % 324, yy = r2 / 18, xx = r2 % 18;
            int gy = ty * 16 - 1 + yy, gx = tx * 16 - 1 + xx;
            float v = 0.f;
            if ((unsigned)gy < 256u && (unsigned)gx < 256u)
                v = in[((n * 64 + ci0 + ci) << 16) + (gy << 8) + gx];
            sIn[ci][yy][xx] = v;
        }
        for (int e = threadIdx.x; e < 4608; e += 256) {
            int co = e / 72, r2 = e % 72, ci = r2 / 9, kk = r2 % 9;
            sW[(ci * 9 + kk) * 68 + co] = Wb[co * 576 + (ci0 + ci) * 9 + kk];
        }
        __syncthreads();

#pragma unroll 1
        for (int ci = 0; ci < 8; ci++) {
            const float* wbase = &sW[ci * 9 * 68 + cobase];
#pragma unroll
            for (int ky = 0; ky < 3; ky++) {
                const float* ip = &sIn[ci][row + ky][col0];
                float4 i0 = *reinterpret_cast<const float4*>(ip);
                float2 i1 = *reinterpret_cast<const float2*>(ip + 4);
                unsigned long long ivp[6];
                ivp[0] = splat2(i0.x); ivp[1] = splat2(i0.y);
                ivp[2] = splat2(i0.z); ivp[3] = splat2(i0.w);
                ivp[4] = splat2(i1.x); ivp[5] = splat2(i1.y);
#pragma unroll
                for (int kx = 0; kx < 3; kx++) {
                    // 8 packed weight pairs = 64B, loaded as 4x 16B
                    const ulonglong2* wp = reinterpret_cast<const ulonglong2*>(
                        wbase + (ky * 3 + kx) * 68);
                    ulonglong2 wa = wp[0], wb2 = wp[1], wc = wp[2], wd = wp[3];
                    unsigned long long w[8] = {wa.x, wa.y, wb2.x, wb2.y,
                                               wc.x, wc.y, wd.x, wd.y};
#pragma unroll
                    for (int c = 0; c < 8; c++) {
                        fma2(acc2[c][0], w[c], ivp[kx + 0]);
                        fma2(acc2[c][1], w[c], ivp[kx + 1]);
                        fma2(acc2[c][2], w[c], ivp[kx + 2]);
                        fma2(acc2[c][3], w[c], ivp[kx + 3]);
                    }
                }
            }
        }
        __syncthreads();
    }

    const float a = aB[0];
    const int gy = ty * 16 + row, gx0 = tx * 16 + col0;
#pragma unroll
    for (int c2 = 0; c2 < 8; c2++) {
        float lo[4], hi[4];
#pragma unroll
        for (int p = 0; p < 4; p++) unpack2(acc2[c2][p], lo[p], hi[p]);

        int baseL = ((n * 64 + cobase + 2 * c2 + 0) << 16) + (gy << 8) + gx0;
        int baseH = ((n * 64 + cobase + 2 * c2 + 1) << 16) + (gy << 8) + gx0;

        float4 vL = make_float4(lo[0], lo[1], lo[2], lo[3]);
        float4 vH = make_float4(hi[0], hi[1], hi[2], hi[3]);
        if (RES) {
            float4 rL = *reinterpret_cast<const float4*>(res + baseL);
            float4 rH = *reinterpret_cast<const float4*>(res + baseH);
            vL.x += rL.x; vL.y += rL.y; vL.z += rL.z; vL.w += rL.w;
            vH.x += rH.x; vH.y += rH.y; vH.z += rH.z; vH.w += rH.w;
        }
        vL.x = prelu_f(vL.x, a); vL.y = prelu_f(vL.y, a);
        vL.z = prelu_f(vL.z, a); vL.w = prelu_f(vL.w, a);
        vH.x = prelu_f(vH.x, a); vH.y = prelu_f(vH.y, a);
        vH.z = prelu_f(vH.z, a); vH.w = prelu_f(vH.w, a);
        *reinterpret_cast<float4*>(out + baseL) = vL;
        *reinterpret_cast<float4*>(out + baseH) = vH;
    }
}

// ---------------------------------------------------------------------------
// Last conv: (feat + initrec broadcast) -> 1 channel, 3x3 pad 1.
// ---------------------------------------------------------------------------
__global__ void last_kernel(const float* __restrict__ feat,
                            const float* __restrict__ initrec,
                            const float* __restrict__ Wl,
                            float* __restrict__ out) {
    const int tx = blockIdx.x, ty = blockIdx.y, n = blockIdx.z;
    __shared__ float sInit[18][18];
    __shared__ float sIn[8][18][20];
    __shared__ float sWl[576];

    for (int e = threadIdx.x; e < 324; e += 256) {
        int yy = e / 18, xx = e % 18;
        int gy = ty * 16 - 1 + yy, gx = tx * 16 - 1 + xx;
        float v = 0.f;
        if ((unsigned)gy < 256u && (unsigned)gx < 256u)
            v = initrec[n * HWSZ + gy * 256 + gx];
        sInit[yy][xx] = v;
    }
    for (int e = threadIdx.x; e < 576; e += 256) sWl[e] = Wl[e];
    __syncthreads();

    const int r = threadIdx.x >> 4, c = threadIdx.x & 15;
    float acc = 0.f;

    for (int ci0 = 0; ci0 < 64; ci0 += 8) {
        for (int e = threadIdx.x; e < 2592; e += 256) {
            int ci = e / 324, r2 = e % 324, yy = r2 / 18, xx = r2 % 18;
            int gy = ty * 16 - 1 + yy, gx = tx * 16 - 1 + xx;
            float v = 0.f;
            if ((unsigned)gy < 256u && (unsigned)gx < 256u)
                v = feat[((n * 64 + ci0 + ci) << 16) + (gy << 8) + gx];
            sIn[ci][yy][xx] = v + sInit[yy][xx];
        }
        __syncthreads();
#pragma unroll 1
        for (int ci = 0; ci < 8; ci++) {
#pragma unroll
            for (int ky = 0; ky < 3; ky++)
#pragma unroll
                for (int kx = 0; kx < 3; kx++)
                    acc += sIn[ci][r + ky][c + kx] * sWl[(ci0 + ci) * 9 + ky * 3 + kx];
        }
        __syncthreads();
    }
    out[n * HWSZ + (ty * 16 + r) * 256 + (tx * 16 + c)] = acc;
}

// ---------------------------------------------------------------------------
extern "C" void kernel_launch(void* const* d_in, const int* in_sizes, int n_in,
                              void* d_out, int out_size) {
    (void)in_sizes; (void)n_in; (void)out_size;
    const float* x   = (const float*)d_in[0];
    const float* Wcs = (const float*)d_in[1];
    const float* Wi  = (const float*)d_in[2];
    const float* Wf  = (const float*)d_in[3];
    const float* Wb  = (const float*)d_in[4];
    const float* Wl  = (const float*)d_in[5];
    const float* aM  = (const float*)d_in[6];
    const float* aB  = (const float*)d_in[7];

    float* out     = (float*)d_out;             // [16,1,256,256]
    float* csy     = out + 16 * HWSZ;           // [16,256,8,8]
    float* initrec = csy + 16 * 256 * 64;       // [16,1,256,256]

    float *fA = nullptr, *fB = nullptr;
    cudaGetSymbolAddress((void**)&fA, g_featA);
    cudaGetSymbolAddress((void**)&fB, g_featB);

    cs_kernel<<<dim3(8, 16), 256>>>(x, Wcs, csy);
    init_kernel<<<dim3(8, 16), 256>>>(csy, Wi, initrec);
    first_kernel<<<dim3(16, 16, 16), 256>>>(initrec, Wf, aM, fA);

    for (int i = 0; i < 4; i++) {
        blk_kernel<false><<<dim3(16, 16, 16), 256>>>(fA, Wb, aB, fB, nullptr);
        blk_kernel<true><<<dim3(16, 16, 16), 256>>>(fB, Wb, aB, fA, fA);
    }
    last_kernel<<<dim3(16, 16, 16), 256>>>(fA, initrec, Wl, out);
}